// round 3
// baseline (speedup 1.0000x reference)
#include <cuda_runtime.h>
#include <cuda_bf16.h>

// Problem constants
#define NB    4      // batch
#define CIN   64
#define COUT  64
#define DIN   64
#define DOUTD 62     // DIN - K + 1
#define STYLE 128
#define HID   128
#define KK    3
#define NT    27     // K^3

typedef unsigned long long u64;

// ---------------- scratch (no cudaMalloc allowed) ----------------
__device__ float g_style[NB * CIN];                       // (n, ci)
__device__ float g_wmod[(size_t)NB * NT * CIN * COUT];    // [n][t][ci][co], t = kz*9+ky*3+kx

// ---------------- packed f32x2 helpers ----------------
__device__ __forceinline__ u64 pk2(float v) {
    u64 r; asm("mov.b64 %0, {%1, %1};" : "=l"(r) : "f"(v)); return r;
}
__device__ __forceinline__ void fma2(u64 &a, u64 b, u64 c) {
    asm("fma.rn.f32x2 %0, %1, %2, %0;" : "+l"(a) : "l"(b), "l"(c));
}
__device__ __forceinline__ float2 upk(u64 a) {
    float2 r; asm("mov.b64 {%0, %1}, %2;" : "=f"(r.x), "=f"(r.y) : "l"(a)); return r;
}
__device__ __forceinline__ float lrelu(float v) { return v > 0.0f ? v : 0.01f * v; }

// ================= kernel 1: style MLP =================
// 1 block, 128 threads. s(4,128) -> h1 -> h2 -> style(4,64)
__global__ void style_mlp_kernel(const float* __restrict__ s,
                                 const float* __restrict__ w1, const float* __restrict__ b1,
                                 const float* __restrict__ w2, const float* __restrict__ b2,
                                 const float* __restrict__ w3, const float* __restrict__ b3) {
    __shared__ float hA[NB][HID];
    __shared__ float hB[NB][HID];
    const int t = threadIdx.x;  // 0..127

    for (int n = 0; n < NB; n++) hA[n][t] = s[n * STYLE + t];
    __syncthreads();

    // layer 1: hB = lrelu(hA @ w1.T + b1)
    {
        float a0 = b1[t], a1 = b1[t], a2 = b1[t], a3 = b1[t];
        const float* wr = w1 + t * STYLE;
        for (int k = 0; k < STYLE; k++) {
            float w = wr[k];
            a0 += hA[0][k] * w; a1 += hA[1][k] * w; a2 += hA[2][k] * w; a3 += hA[3][k] * w;
        }
        hB[0][t] = lrelu(a0); hB[1][t] = lrelu(a1); hB[2][t] = lrelu(a2); hB[3][t] = lrelu(a3);
    }
    __syncthreads();

    // layer 2: hA = lrelu(hB @ w2.T + b2)
    {
        float a0 = b2[t], a1 = b2[t], a2 = b2[t], a3 = b2[t];
        const float* wr = w2 + t * HID;
        for (int k = 0; k < HID; k++) {
            float w = wr[k];
            a0 += hB[0][k] * w; a1 += hB[1][k] * w; a2 += hB[2][k] * w; a3 += hB[3][k] * w;
        }
        hA[0][t] = lrelu(a0); hA[1][t] = lrelu(a1); hA[2][t] = lrelu(a2); hA[3][t] = lrelu(a3);
    }
    __syncthreads();

    // layer 3: style = hA @ w3.T + b3   (CIN=64 outputs)
    if (t < CIN) {
        float a0 = b3[t], a1 = b3[t], a2 = b3[t], a3 = b3[t];
        const float* wr = w3 + t * HID;
        for (int k = 0; k < HID; k++) {
            float w = wr[k];
            a0 += hA[0][k] * w; a1 += hA[1][k] * w; a2 += hA[2][k] * w; a3 += hA[3][k] * w;
        }
        g_style[0 * CIN + t] = a0;
        g_style[1 * CIN + t] = a1;
        g_style[2 * CIN + t] = a2;
        g_style[3 * CIN + t] = a3;
    }
}

// ================= kernel 2: modulate + demodulate =================
// One block per (n, co). weight layout: [co][ci][kz][ky][kx] (co*1728 + ci*27 + t)
// Output g_wmod[n][t][ci][co] = w * style[n][ci] * rsqrt(sum + eps)
__global__ void modulate_kernel(const float* __restrict__ weight) {
    const int b  = blockIdx.x;
    const int n  = b >> 6;
    const int co = b & 63;
    const int tid = threadIdx.x;  // 256

    __shared__ float buf[CIN * NT];   // 1728
    __shared__ float red[8];

    const float* wco = weight + (size_t)co * (CIN * NT);
    float ssum = 0.0f;
    for (int i = tid; i < CIN * NT; i += 256) {
        int ci = i / NT;
        float m = wco[i] * g_style[n * CIN + ci];
        buf[i] = m;
        ssum += m * m;
    }
    // block reduce
    for (int o = 16; o; o >>= 1) ssum += __shfl_xor_sync(0xFFFFFFFFu, ssum, o);
    if ((tid & 31) == 0) red[tid >> 5] = ssum;
    __syncthreads();
    float tot = 0.0f;
    #pragma unroll
    for (int j = 0; j < 8; j++) tot += red[j];
    const float inv = rsqrtf(tot + 1e-8f);

    for (int i = tid; i < CIN * NT; i += 256) {
        int ci = i / NT;
        int tt = i - ci * NT;
        g_wmod[(((size_t)n * NT + tt) * CIN + ci) * COUT + co] = buf[i] * inv;
    }
}

// ================= kernel 3: conv (implicit GEMM, f32x2 packed) =================
// Block = (n, zo, 2 output y-rows). Tile: 64 Cout x (2 rows x 64 padded x).
// SMEM: xS[ci][4 rows][68]   (4 rows cover ky 0..2 over 2 out rows; pad 64..67 zero)
//       wS[kx][ci][co]       (3 kx slices of 64x64)
#define XS_STRIDE 68
#define XS_WORDS (CIN * 4 * XS_STRIDE)     // 17408
#define WS_WORDS (3 * CIN * COUT)          // 12288
#define CONV_SMEM_BYTES ((XS_WORDS + WS_WORDS) * 4)

__global__ void __launch_bounds__(256, 1)
conv_kernel(const float* __restrict__ x, float* __restrict__ y) {
    extern __shared__ float sm[];
    float* xS = sm;               // [ci][r][68]
    float* wS = sm + XS_WORDS;    // [kx][ci][co]

    const int tid = threadIdx.x;
    const int n   = blockIdx.z;
    const int zo  = blockIdx.y;
    const int yo0 = blockIdx.x * 2;

    const int sp_g  = tid & 15;          // 16 spatial groups
    const int co0   = (tid >> 4) * 4;    // 4 couts per thread
    const int r_out = sp_g >> 3;         // 0/1: which output row
    const int xb    = (sp_g & 7) * 8;    // 8 consecutive x per thread

    // zero the x-pad region [64..67] once (persists: loads only touch [0..63])
    {
        int ci = tid >> 2, r = tid & 3;  // 256 threads = 64ci*4r
        float* p = &xS[(ci * 4 + r) * XS_STRIDE + 64];
        p[0] = 0.f; p[1] = 0.f; p[2] = 0.f; p[3] = 0.f;
    }

    u64 acc[2][8];
    #pragma unroll
    for (int a = 0; a < 2; a++)
        #pragma unroll
        for (int b = 0; b < 8; b++) acc[a][b] = 0ull;

    const float* xn = x + (size_t)n * CIN * DIN * DIN * DIN;

    #pragma unroll 1
    for (int kz = 0; kz < 3; kz++) {
        __syncthreads();   // previous GEMM done (and pad writes on first pass)
        // ---- load xS: 4 rows (yo0..yo0+3) at z_in = zo+kz, all 64 ci ----
        {
            const int z_in = zo + kz;
            #pragma unroll
            for (int it = 0; it < 16; it++) {           // 4096 float4 / 256 threads
                int i  = tid + it * 256;
                int x4 = i & 15;
                int ci = (i >> 4) & 63;
                int r  = i >> 10;
                float4 v = *(const float4*)(xn + (((size_t)ci * DIN + z_in) * DIN + (yo0 + r)) * DIN + x4 * 4);
                *(float4*)&xS[(ci * 4 + r) * XS_STRIDE + x4 * 4] = v;
            }
        }
        #pragma unroll 1
        for (int ky = 0; ky < 3; ky++) {
            __syncthreads();   // xS visible / previous wS consumers done
            // ---- load wS: 3 contiguous kx slices for t0 = kz*9+ky*3 ----
            {
                const float* wsrc = g_wmod + ((size_t)(n * NT + kz * 9 + ky * 3)) * (CIN * COUT);
                #pragma unroll
                for (int it = 0; it < 12; it++) {       // 3072 float4 / 256 threads
                    int i = tid + it * 256;
                    *(float4*)&wS[i * 4] = *(const float4*)(wsrc + i * 4);
                }
            }
            __syncthreads();

            const float* xrow = &xS[(r_out + ky) * XS_STRIDE + xb];
            #pragma unroll 2
            for (int ci = 0; ci < CIN; ci++) {
                const float* xp = xrow + ci * 4 * XS_STRIDE;
                float4 a0 = *(const float4*)(xp);
                float4 a1 = *(const float4*)(xp + 4);
                float2 a2 = *(const float2*)(xp + 8);
                u64 xd[10];
                xd[0] = pk2(a0.x); xd[1] = pk2(a0.y); xd[2] = pk2(a0.z); xd[3] = pk2(a0.w);
                xd[4] = pk2(a1.x); xd[5] = pk2(a1.y); xd[6] = pk2(a1.z); xd[7] = pk2(a1.w);
                xd[8] = pk2(a2.x); xd[9] = pk2(a2.y);
                #pragma unroll
                for (int kx = 0; kx < 3; kx++) {
                    ulonglong2 wv = *(const ulonglong2*)&wS[(kx * CIN + ci) * COUT + co0];
                    #pragma unroll
                    for (int sp = 0; sp < 8; sp++) {
                        fma2(acc[0][sp], wv.x, xd[sp + kx]);
                        fma2(acc[1][sp], wv.y, xd[sp + kx]);
                    }
                }
            }
        }
    }

    // ---- store: 4 couts x 8 x-positions (mask x >= 62) ----
    const int yo = yo0 + r_out;
    const size_t COS = (size_t)DOUTD * DOUTD * DOUTD;   // cout stride
    const size_t outb = (((size_t)(n * COUT + co0) * DOUTD + zo) * DOUTD + yo) * DOUTD;
    #pragma unroll
    for (int sp = 0; sp < 8; sp++) {
        int xo = xb + sp;
        if (xo < DOUTD) {
            float2 v0 = upk(acc[0][sp]);
            float2 v1 = upk(acc[1][sp]);
            y[outb + xo]           = v0.x;
            y[outb + COS + xo]     = v0.y;
            y[outb + 2 * COS + xo] = v1.x;
            y[outb + 3 * COS + xo] = v1.y;
        }
    }
}

// ================= launch =================
extern "C" void kernel_launch(void* const* d_in, const int* in_sizes, int n_in,
                              void* d_out, int out_size) {
    const float* x      = (const float*)d_in[0];
    const float* s      = (const float*)d_in[1];
    const float* w1     = (const float*)d_in[2];
    const float* b1     = (const float*)d_in[3];
    const float* w2     = (const float*)d_in[4];
    const float* b2     = (const float*)d_in[5];
    const float* w3     = (const float*)d_in[6];
    const float* b3     = (const float*)d_in[7];
    const float* weight = (const float*)d_in[8];
    float* y = (float*)d_out;

    cudaFuncSetAttribute(conv_kernel, cudaFuncAttributeMaxDynamicSharedMemorySize, CONV_SMEM_BYTES);

    style_mlp_kernel<<<1, 128>>>(s, w1, b1, w2, b2, w3, b3);
    modulate_kernel<<<NB * COUT, 256>>>(weight);
    conv_kernel<<<dim3(DOUTD / 2, DOUTD, NB), 256, CONV_SMEM_BYTES>>>(x, y);
}